// round 1
// baseline (speedup 1.0000x reference)
#include <cuda_runtime.h>
#include <cuda_bf16.h>
#include <math.h>

// Problem constants (fixed by the dataset)
#define Bt      16384          // G*S tokens
#define Dd      256
#define Hh      512
#define Ee      8
#define Kk      2
#define TILE_M  128
#define ROWS_CAP (Bt*Kk + Ee*TILE_M)     // 33792 (expert segments padded to 128)
#define MAX_TILES (ROWS_CAP / TILE_M)    // 264

// ---------------- scratch (static __device__, no allocation) ----------------
__device__ float g_act[(size_t)ROWS_CAP * Hh];   // gated activations (C x H)
__device__ int   g_tok[ROWS_CAP];                 // token id per sorted row
__device__ float g_wrow[ROWS_CAP];                // combine weight * per_expert_scale
__device__ int   g_choice[Bt * Kk];
__device__ float g_weight[Bt * Kk];
__device__ int   g_counts[Ee];
__device__ int   g_cursor[Ee];
__device__ int   g_pstart[Ee + 1];

// ---------------- helpers ----------------
__device__ __forceinline__ float gelu_tanh(float v) {
    const float c = 0.7978845608028654f;
    float t = tanhf(c * (v + 0.044715f * v * v * v));
    return 0.5f * v * (1.f + t);
}

// ---------------- init: zero counters ----------------
__global__ void init_kernel() {
    int i = threadIdx.x;
    if (i < Ee) { g_counts[i] = 0; g_cursor[i] = 0; }
}

// ---------------- router: RMSnorm + logits + softmax-top2 weights ----------------
__global__ void __launch_bounds__(256) router_kernel(const float* __restrict__ x,
                                                     const float* __restrict__ wr,
                                                     const float* __restrict__ rsc) {
    int warp = threadIdx.x >> 5;
    int lane = threadIdx.x & 31;
    int t = blockIdx.x * 8 + warp;
    const float* xr = x + (size_t)t * Dd;

    float sumsq = 0.f;
    float l[8] = {0.f,0.f,0.f,0.f,0.f,0.f,0.f,0.f};
#pragma unroll
    for (int i = 0; i < 8; i++) {
        int d = i * 32 + lane;
        float xv = xr[d];
        sumsq += xv * xv;
        float xs = xv * rsc[d];
        float4 w0 = *(const float4*)(wr + d * 8);
        float4 w1 = *(const float4*)(wr + d * 8 + 4);
        l[0] += xs * w0.x; l[1] += xs * w0.y; l[2] += xs * w0.z; l[3] += xs * w0.w;
        l[4] += xs * w1.x; l[5] += xs * w1.y; l[6] += xs * w1.z; l[7] += xs * w1.w;
    }
#pragma unroll
    for (int off = 16; off; off >>= 1) {
        sumsq += __shfl_xor_sync(0xffffffffu, sumsq, off);
#pragma unroll
        for (int e = 0; e < 8; e++) l[e] += __shfl_xor_sync(0xffffffffu, l[e], off);
    }
    if (lane == 0) {
        float s = rsqrtf(sumsq * (1.f / Dd) + 1e-6f) * rsqrtf((float)Dd);
        float lg[8];
#pragma unroll
        for (int e = 0; e < 8; e++) lg[e] = l[e] * s;
        // exact top-2, lowest-index tie-break (matches jax top_k)
        int i1 = 0;
#pragma unroll
        for (int e = 1; e < 8; e++) if (lg[e] > lg[i1]) i1 = e;
        int i2 = (i1 == 0) ? 1 : 0;
#pragma unroll
        for (int e = 0; e < 8; e++) if (e != i1 && e > i2 && lg[e] > lg[i2]) i2 = e;
        // also allow e < current i2 start (init already the smallest non-i1 index)
        // weights: softmax denominator cancels against renorm
        float p2 = expf(lg[i2] - lg[i1]);
        float inv = 1.f / (1.f + p2);
        g_choice[2 * t]     = i1;
        g_choice[2 * t + 1] = i2;
        g_weight[2 * t]     = inv;
        g_weight[2 * t + 1] = p2 * inv;
        atomicAdd(&g_counts[i1], 1);
        atomicAdd(&g_counts[i2], 1);
    }
}

// ---------------- prefix: padded segment starts ----------------
__global__ void prefix_kernel() {
    if (threadIdx.x == 0) {
        int p = 0;
#pragma unroll
        for (int e = 0; e < Ee; e++) {
            g_pstart[e] = p;
            p += (g_counts[e] + TILE_M - 1) & ~(TILE_M - 1);
        }
        g_pstart[Ee] = p;
    }
}

// ---------------- scatter: assign rows to expert segments ----------------
__global__ void scatter_kernel(const float* __restrict__ pes) {
    int t = blockIdx.x * blockDim.x + threadIdx.x;
    if (t >= Bt) return;
#pragma unroll
    for (int j = 0; j < 2; j++) {
        int c = g_choice[2 * t + j];
        int r = atomicAdd(&g_cursor[c], 1);
        int pos = g_pstart[c] + r;
        g_tok[pos]  = t;
        g_wrow[pos] = g_weight[2 * t + j] * pes[c];
    }
}

// ---------------- shared tile-meta lookup ----------------
__device__ __forceinline__ void tile_meta(int row0, int& e_out, int& active_out) {
    int e = -1, active = 0;
    int total = g_pstart[Ee];
    if (row0 < total) {
#pragma unroll
        for (int i = 0; i < Ee; i++)
            if (row0 >= g_pstart[i] && row0 < g_pstart[i + 1]) { e = i; break; }
        active = min(TILE_M, g_counts[e] - (row0 - g_pstart[e]));
    }
    e_out = e; active_out = active;
}

// ---------------- ffn1: X(rows x 256) @ Wg^T -> gelu-gate -> act(rows x 512) ----------------
// virtual N = 1024 (interleaved mat0/mat1 columns: vc = f*2 + m)
__global__ void __launch_bounds__(256) ffn1_kernel(const float* __restrict__ x,
                                                   const float* __restrict__ wg) {
    __shared__ __align__(16) float As[16][TILE_M];
    __shared__ __align__(16) float Bs[16][TILE_M];
    __shared__ int s_tok[TILE_M];
    __shared__ int s_meta[2];

    int tid = threadIdx.x;
    int row0 = blockIdx.x * TILE_M;
    if (tid == 0) { int e, a; tile_meta(row0, e, a); s_meta[0] = e; s_meta[1] = a; }
    __syncthreads();
    int e = s_meta[0], active = s_meta[1];
    if (active <= 0) return;
    if (tid < TILE_M) s_tok[tid] = (tid < active) ? g_tok[row0 + tid] : -1;
    __syncthreads();

    int m  = tid >> 1;              // 0..127 : A-row / B-col loaded by this thread
    int kq = (tid & 1) * 8;         // 0 or 8 : k offset
    int tok = s_tok[m];
    const float* arow = (tok >= 0) ? (x + (size_t)tok * Dd) : nullptr;
    int vc  = blockIdx.y * TILE_M + m;              // virtual column 0..1023
    const float* brow = wg + ((size_t)(e * 2 + (vc & 1)) * Hh + (vc >> 1)) * Dd;

    int tm = (tid >> 4) * 8;        // microtile row
    int tn = (tid & 15) * 8;        // microtile col
    float acc[8][8];
#pragma unroll
    for (int i = 0; i < 8; i++)
#pragma unroll
        for (int j = 0; j < 8; j++) acc[i][j] = 0.f;

    for (int k0 = 0; k0 < Dd; k0 += 16) {
        float4 a0 = make_float4(0.f,0.f,0.f,0.f), a1 = a0;
        if (arow) { a0 = *(const float4*)(arow + k0 + kq);
                    a1 = *(const float4*)(arow + k0 + kq + 4); }
        float4 b0 = *(const float4*)(brow + k0 + kq);
        float4 b1 = *(const float4*)(brow + k0 + kq + 4);
        __syncthreads();
        As[kq+0][m]=a0.x; As[kq+1][m]=a0.y; As[kq+2][m]=a0.z; As[kq+3][m]=a0.w;
        As[kq+4][m]=a1.x; As[kq+5][m]=a1.y; As[kq+6][m]=a1.z; As[kq+7][m]=a1.w;
        Bs[kq+0][m]=b0.x; Bs[kq+1][m]=b0.y; Bs[kq+2][m]=b0.z; Bs[kq+3][m]=b0.w;
        Bs[kq+4][m]=b1.x; Bs[kq+5][m]=b1.y; Bs[kq+6][m]=b1.z; Bs[kq+7][m]=b1.w;
        __syncthreads();
#pragma unroll
        for (int k = 0; k < 16; k++) {
            float4 av0 = *(const float4*)&As[k][tm];
            float4 av1 = *(const float4*)&As[k][tm + 4];
            float4 bv0 = *(const float4*)&Bs[k][tn];
            float4 bv1 = *(const float4*)&Bs[k][tn + 4];
            float a[8] = {av0.x,av0.y,av0.z,av0.w,av1.x,av1.y,av1.z,av1.w};
            float b[8] = {bv0.x,bv0.y,bv0.z,bv0.w,bv1.x,bv1.y,bv1.z,bv1.w};
#pragma unroll
            for (int i = 0; i < 8; i++)
#pragma unroll
                for (int j = 0; j < 8; j++) acc[i][j] += a[i] * b[j];
        }
    }

    // epilogue: gelu(x1)*x2 ; each pair of virtual cols -> one f
    int f0 = blockIdx.y * (TILE_M / 2) + (tn >> 1);
#pragma unroll
    for (int i = 0; i < 8; i++) {
        int r = tm + i;
        if (r >= active) continue;
        float4 o;
        o.x = gelu_tanh(acc[i][0]) * acc[i][1];
        o.y = gelu_tanh(acc[i][2]) * acc[i][3];
        o.z = gelu_tanh(acc[i][4]) * acc[i][5];
        o.w = gelu_tanh(acc[i][6]) * acc[i][7];
        *(float4*)&g_act[(size_t)(row0 + r) * Hh + f0] = o;
    }
}

// ---------------- ffn2: act(rows x 512) @ Wl -> scaled atomic combine into out ----------------
__global__ void __launch_bounds__(256) ffn2_kernel(const float* __restrict__ wl,
                                                   float* __restrict__ out) {
    __shared__ __align__(16) float As[16][TILE_M];
    __shared__ __align__(16) float Bs[16][TILE_M];
    __shared__ int s_meta[2];

    int tid = threadIdx.x;
    int row0 = blockIdx.x * TILE_M;
    if (tid == 0) { int e, a; tile_meta(row0, e, a); s_meta[0] = e; s_meta[1] = a; }
    __syncthreads();
    int e = s_meta[0], active = s_meta[1];
    if (active <= 0) return;

    int m  = tid >> 1;
    int kq = (tid & 1) * 8;
    bool aval = (m < active);
    const float* arow = g_act + (size_t)(row0 + m) * Hh;

    int kk = tid >> 4;              // 0..15 : B k-row loaded by this thread
    int nq = (tid & 15) * 8;        // 0..120
    const float* bbase = wl + (size_t)e * Hh * Dd + blockIdx.y * TILE_M + nq;

    int tm = (tid >> 4) * 8;
    int tn = (tid & 15) * 8;
    float acc[8][8];
#pragma unroll
    for (int i = 0; i < 8; i++)
#pragma unroll
        for (int j = 0; j < 8; j++) acc[i][j] = 0.f;

    for (int k0 = 0; k0 < Hh; k0 += 16) {
        float4 a0 = make_float4(0.f,0.f,0.f,0.f), a1 = a0;
        if (aval) { a0 = *(const float4*)(arow + k0 + kq);
                    a1 = *(const float4*)(arow + k0 + kq + 4); }
        float4 b0 = *(const float4*)(bbase + (size_t)(k0 + kk) * Dd);
        float4 b1 = *(const float4*)(bbase + (size_t)(k0 + kk) * Dd + 4);
        __syncthreads();
        As[kq+0][m]=a0.x; As[kq+1][m]=a0.y; As[kq+2][m]=a0.z; As[kq+3][m]=a0.w;
        As[kq+4][m]=a1.x; As[kq+5][m]=a1.y; As[kq+6][m]=a1.z; As[kq+7][m]=a1.w;
        *(float4*)&Bs[kk][nq]     = b0;
        *(float4*)&Bs[kk][nq + 4] = b1;
        __syncthreads();
#pragma unroll
        for (int k = 0; k < 16; k++) {
            float4 av0 = *(const float4*)&As[k][tm];
            float4 av1 = *(const float4*)&As[k][tm + 4];
            float4 bv0 = *(const float4*)&Bs[k][tn];
            float4 bv1 = *(const float4*)&Bs[k][tn + 4];
            float a[8] = {av0.x,av0.y,av0.z,av0.w,av1.x,av1.y,av1.z,av1.w};
            float b[8] = {bv0.x,bv0.y,bv0.z,bv0.w,bv1.x,bv1.y,bv1.z,bv1.w};
#pragma unroll
            for (int i = 0; i < 8; i++)
#pragma unroll
                for (int j = 0; j < 8; j++) acc[i][j] += a[i] * b[j];
        }
    }

    int n0 = blockIdx.y * TILE_M;
#pragma unroll
    for (int i = 0; i < 8; i++) {
        int r = tm + i;
        if (r >= active) continue;
        int row = row0 + r;
        float w = g_wrow[row];
        float* obase = out + (size_t)g_tok[row] * Dd + n0 + tn;
#pragma unroll
        for (int j = 0; j < 8; j++) atomicAdd(obase + j, acc[i][j] * w);
    }
}

// ---------------- launch ----------------
extern "C" void kernel_launch(void* const* d_in, const int* in_sizes, int n_in,
                              void* d_out, int out_size) {
    const float* x   = (const float*)d_in[0];
    const float* wr  = (const float*)d_in[1];
    const float* wg  = (const float*)d_in[2];
    const float* wl  = (const float*)d_in[3];
    const float* pes = (const float*)d_in[4];
    const float* rsc = (const float*)d_in[5];
    float* out = (float*)d_out;

    cudaMemsetAsync(out, 0, (size_t)out_size * sizeof(float), 0);
    init_kernel<<<1, 32>>>();
    router_kernel<<<Bt / 8, 256>>>(x, wr, rsc);
    prefix_kernel<<<1, 32>>>();
    scatter_kernel<<<Bt / 256, 256>>>(pes);
    ffn1_kernel<<<dim3(MAX_TILES, 8), 256>>>(x, wg);
    ffn2_kernel<<<dim3(MAX_TILES, 2), 256>>>(wl, out);
}

// round 4
// speedup vs baseline: 2.1658x; 2.1658x over previous
#include <cuda_runtime.h>
#include <cuda_bf16.h>
#include <math.h>
#include <stdint.h>

// Problem constants (fixed by the dataset)
#define Bt      16384
#define Dd      256
#define Hh      512
#define Ee      8
#define Kk      2
#define TILE_M  128
#define ROWS_CAP (Bt*Kk + Ee*TILE_M)     // 33792
#define MAX_TILES (ROWS_CAP / TILE_M)    // 264

// A/B SMEM tile: 128 rows x 32 floats, stride 36 (bank-conflict-free frags)
#define KCH     32
#define LDT     36
#define TILE_F  (TILE_M * LDT)           // 4608 floats per tile

// ---------------- scratch ----------------
__device__ float g_act[(size_t)ROWS_CAP * Hh];
__device__ float g_wlt[(size_t)Ee * Dd * Hh];     // wl transposed: [e][d][f]
__device__ int   g_tok[ROWS_CAP];
__device__ float g_wrow[ROWS_CAP];
__device__ int   g_choice[Bt * Kk];
__device__ float g_weight[Bt * Kk];
__device__ int   g_counts[Ee];
__device__ int   g_cursor[Ee];
__device__ int   g_pstart[Ee + 1];

// ---------------- helpers ----------------
__device__ __forceinline__ float gelu_tanh(float v) {
    const float c = 0.7978845608028654f;
    float t = tanhf(c * (v + 0.044715f * v * v * v));
    return 0.5f * v * (1.f + t);
}
__device__ __forceinline__ uint32_t f2tf32(float f) {
    uint32_t r;
    asm("cvt.rna.tf32.f32 %0, %1;" : "=r"(r) : "f"(f));
    return r;
}
__device__ __forceinline__ void mma_tf32(float* c, const uint32_t* a, const uint32_t* b) {
    asm volatile(
        "mma.sync.aligned.m16n8k8.row.col.f32.tf32.tf32.f32 "
        "{%0,%1,%2,%3}, {%4,%5,%6,%7}, {%8,%9}, {%0,%1,%2,%3};"
        : "+f"(c[0]), "+f"(c[1]), "+f"(c[2]), "+f"(c[3])
        : "r"(a[0]), "r"(a[1]), "r"(a[2]), "r"(a[3]), "r"(b[0]), "r"(b[1]));
}
__device__ __forceinline__ uint32_t smem_u32(const void* p) {
    uint32_t a;
    asm("{ .reg .u64 t; cvta.to.shared.u64 t, %1; cvt.u32.u64 %0, t; }" : "=r"(a) : "l"(p));
    return a;
}
#define CP_ASYNC16(sm, gp) asm volatile("cp.async.cg.shared.global [%0], [%1], 16;" :: "r"(sm), "l"(gp))
#define CP_COMMIT()        asm volatile("cp.async.commit_group;")
#define CP_WAIT(n)         asm volatile("cp.async.wait_group %0;" :: "n"(n))

// ---------------- small kernels ----------------
__global__ void init_kernel() {
    int i = threadIdx.x;
    if (i < Ee) { g_counts[i] = 0; g_cursor[i] = 0; }
}

__global__ void __launch_bounds__(256) router_kernel(const float* __restrict__ x,
                                                     const float* __restrict__ wr,
                                                     const float* __restrict__ rsc) {
    int warp = threadIdx.x >> 5, lane = threadIdx.x & 31;
    int t = blockIdx.x * 8 + warp;
    const float* xr = x + (size_t)t * Dd;
    float sumsq = 0.f;
    float l[8] = {0,0,0,0,0,0,0,0};
#pragma unroll
    for (int i = 0; i < 8; i++) {
        int d = i * 32 + lane;
        float xv = xr[d];
        sumsq += xv * xv;
        float xs = xv * rsc[d];
        float4 w0 = *(const float4*)(wr + d * 8);
        float4 w1 = *(const float4*)(wr + d * 8 + 4);
        l[0] += xs * w0.x; l[1] += xs * w0.y; l[2] += xs * w0.z; l[3] += xs * w0.w;
        l[4] += xs * w1.x; l[5] += xs * w1.y; l[6] += xs * w1.z; l[7] += xs * w1.w;
    }
#pragma unroll
    for (int off = 16; off; off >>= 1) {
        sumsq += __shfl_xor_sync(0xffffffffu, sumsq, off);
#pragma unroll
        for (int e = 0; e < 8; e++) l[e] += __shfl_xor_sync(0xffffffffu, l[e], off);
    }
    if (lane == 0) {
        float s = rsqrtf(sumsq * (1.f / Dd) + 1e-6f) * rsqrtf((float)Dd);
        float lg[8];
#pragma unroll
        for (int e = 0; e < 8; e++) lg[e] = l[e] * s;
        int i1 = 0;
#pragma unroll
        for (int e = 1; e < 8; e++) if (lg[e] > lg[i1]) i1 = e;
        int i2 = (i1 == 0) ? 1 : 0;
#pragma unroll
        for (int e = 0; e < 8; e++) if (e != i1 && e > i2 && lg[e] > lg[i2]) i2 = e;
        float p2 = expf(lg[i2] - lg[i1]);
        float inv = 1.f / (1.f + p2);
        g_choice[2*t] = i1;  g_choice[2*t+1] = i2;
        g_weight[2*t] = inv; g_weight[2*t+1] = p2 * inv;
    }
}

__global__ void __launch_bounds__(256) count_kernel() {
    __shared__ int h[Ee];
    int tid = threadIdx.x;
    if (tid < Ee) h[tid] = 0;
    __syncthreads();
    int base = blockIdx.x * 512 + tid * 2;
    atomicAdd(&h[g_choice[base]], 1);
    atomicAdd(&h[g_choice[base + 1]], 1);
    __syncthreads();
    if (tid < Ee) atomicAdd(&g_counts[tid], h[tid]);
}

__global__ void prefix_kernel() {
    if (threadIdx.x == 0) {
        int p = 0;
#pragma unroll
        for (int e = 0; e < Ee; e++) {
            g_pstart[e] = p;
            p += (g_counts[e] + TILE_M - 1) & ~(TILE_M - 1);
        }
        g_pstart[Ee] = p;
    }
}

__global__ void __launch_bounds__(256) scatter_kernel(const float* __restrict__ pes) {
    __shared__ int scnt[Ee];
    __shared__ int sbase[Ee];
    int tid = threadIdx.x;
    if (tid < Ee) scnt[tid] = 0;
    __syncthreads();
    int t = blockIdx.x * 256 + tid;
    int c0 = g_choice[2*t], c1 = g_choice[2*t + 1];
    int s0 = atomicAdd(&scnt[c0], 1);
    int s1 = atomicAdd(&scnt[c1], 1);
    __syncthreads();
    if (tid < Ee) sbase[tid] = atomicAdd(&g_cursor[tid], scnt[tid]);
    __syncthreads();
    int p0 = g_pstart[c0] + sbase[c0] + s0;
    int p1 = g_pstart[c1] + sbase[c1] + s1;
    g_tok[p0] = t;  g_wrow[p0] = g_weight[2*t]     * pes[c0];
    g_tok[p1] = t;  g_wrow[p1] = g_weight[2*t + 1] * pes[c1];
}

// transpose wl (E,H,D) -> g_wlt (E,D,H)
__global__ void transpose_wl_kernel(const float* __restrict__ wl) {
    __shared__ float tb[32][33];
    int f0 = blockIdx.x * 32, d0 = blockIdx.y * 32, e = blockIdx.z;
    int tx = threadIdx.x, ty = threadIdx.y;
#pragma unroll
    for (int j = 0; j < 4; j++)
        tb[ty + j*8][tx] = wl[((size_t)e * Hh + (f0 + ty + j*8)) * Dd + d0 + tx];
    __syncthreads();
#pragma unroll
    for (int j = 0; j < 4; j++)
        g_wlt[((size_t)e * Dd + d0 + ty + j*8) * Hh + f0 + tx] = tb[tx][ty + j*8];
}

// ---------------- tile meta ----------------
__device__ __forceinline__ void tile_meta(int row0, int& e_out, int& active_out) {
    int e = -1, active = 0;
    if (row0 < g_pstart[Ee]) {
#pragma unroll
        for (int i = 0; i < Ee; i++)
            if (row0 >= g_pstart[i] && row0 < g_pstart[i + 1]) { e = i; break; }
        active = min(TILE_M, g_counts[e] - (row0 - g_pstart[e]));
    }
    e_out = e; active_out = active;
}

// ---------------- fragment compute (shared by both GEMMs) ----------------
// warp tile 64x32; 8 warps (2 row x 4 col) -> block 128x128
__device__ __forceinline__ void compute_chunk(const float* __restrict__ As,
                                              const float* __restrict__ Bs,
                                              int lane, int wr, int wc,
                                              float acc[4][4][4]) {
#pragma unroll
    for (int kk = 0; kk < 4; kk++) {
        int ko = kk * 8;
        uint32_t a[4][4], b[4][2];
#pragma unroll
        for (int mf = 0; mf < 4; mf++) {
            int r0 = wr*64 + mf*16 + (lane >> 2);
            const float* p0 = As + r0*LDT + ko + (lane & 3);
            a[mf][0] = f2tf32(p0[0]);
            a[mf][1] = f2tf32(p0[8*LDT]);
            a[mf][2] = f2tf32(p0[4]);
            a[mf][3] = f2tf32(p0[8*LDT + 4]);
        }
#pragma unroll
        for (int nf = 0; nf < 4; nf++) {
            int c0 = wc*32 + nf*8 + (lane >> 2);
            const float* p0 = Bs + c0*LDT + ko + (lane & 3);
            b[nf][0] = f2tf32(p0[0]);
            b[nf][1] = f2tf32(p0[4]);
        }
#pragma unroll
        for (int mf = 0; mf < 4; mf++)
#pragma unroll
            for (int nf = 0; nf < 4; nf++)
                mma_tf32(acc[mf][nf], a[mf], b[nf]);
    }
}

// ==================================================================
// ffn1: rows x Wg^T, virtual N=1024 (vc = f*2 + mat), gelu-gate -> g_act
// grid (MAX_TILES, 8); block 256
// ==================================================================
__global__ void __launch_bounds__(256, 2) ffn1_mma(const float* __restrict__ x,
                                                   const float* __restrict__ wg) {
    __shared__ int sMeta[2];
    __shared__ int sTok[TILE_M];
    extern __shared__ float smem[];   // A0 | B0 | A1 | B1 (TILE_F each)

    int tid = threadIdx.x;
    int row0 = blockIdx.x * TILE_M;
    int by = blockIdx.y;
    if (tid == 0) { int e, a; tile_meta(row0, e, a); sMeta[0] = e; sMeta[1] = a; }
    __syncthreads();
    int e = sMeta[0], active = sMeta[1];
    if (active <= 0) return;
    if (tid < TILE_M) sTok[tid] = (tid < active) ? g_tok[row0 + tid] : 0;
    __syncthreads();

    // loader mapping: 2 threads/row, 16 floats each (4x 16B)
    int lrow = tid >> 1, lpart = (tid & 1) * 16;
    const float* xrow = x + (size_t)sTok[lrow] * Dd + lpart;
    int vc = by * TILE_M + lrow;                 // virtual col
    const float* brow = wg + ((size_t)(e*2 + (vc & 1)) * Hh + (vc >> 1)) * Dd + lpart;
    uint32_t sA = smem_u32(smem) + (uint32_t)(lrow*LDT + lpart) * 4u;
    uint32_t sB = sA + TILE_F * 4u;

    int lane = tid & 31, warp = tid >> 5;
    int wr = warp >> 2, wc = warp & 3;
    float acc[4][4][4];
#pragma unroll
    for (int i = 0; i < 4; i++)
#pragma unroll
        for (int j = 0; j < 4; j++)
#pragma unroll
            for (int q = 0; q < 4; q++) acc[i][j][q] = 0.f;

    const int NCH = Dd / KCH;   // 8
    // prologue
#pragma unroll
    for (int i = 0; i < 4; i++) {
        CP_ASYNC16(sA + i*16, xrow + i*4);
        CP_ASYNC16(sB + i*16, brow + i*4);
    }
    CP_COMMIT();
    for (int s = 0; s < NCH; s++) {
        int buf = s & 1;
        if (s + 1 < NCH) {
            uint32_t dA = smem_u32(smem) + (uint32_t)((1-buf)*2*TILE_F + lrow*LDT + lpart)*4u;
            uint32_t dB = dA + TILE_F * 4u;
            const float* gx = xrow + (s+1)*KCH;
            const float* gb = brow + (s+1)*KCH;
#pragma unroll
            for (int i = 0; i < 4; i++) {
                CP_ASYNC16(dA + i*16, gx + i*4);
                CP_ASYNC16(dB + i*16, gb + i*4);
            }
            CP_COMMIT();
            CP_WAIT(1);
        } else {
            CP_WAIT(0);
        }
        __syncthreads();
        const float* As = smem + buf*2*TILE_F;
        compute_chunk(As, As + TILE_F, lane, wr, wc, acc);
        __syncthreads();
    }

    // epilogue: gelu(even vc)*odd vc -> g_act (all 128 rows; garbage rows finite)
    int rbase = row0 + wr*64 + (lane >> 2);
    int fbase = by*64 + wc*16 + (lane & 3);
#pragma unroll
    for (int mf = 0; mf < 4; mf++) {
        int r = rbase + mf*16;
#pragma unroll
        for (int nf = 0; nf < 4; nf++) {
            int f = fbase + nf*4;
            g_act[(size_t)r * Hh + f]       = gelu_tanh(acc[mf][nf][0]) * acc[mf][nf][1];
            g_act[(size_t)(r+8) * Hh + f]   = gelu_tanh(acc[mf][nf][2]) * acc[mf][nf][3];
        }
    }
}

// ==================================================================
// ffn2: act x wlt[e]^T (128 x 256 x 512), scale, atomic combine into out
// grid (MAX_TILES, 2); block 256
// ==================================================================
__global__ void __launch_bounds__(256, 2) ffn2_mma(float* __restrict__ out) {
    __shared__ int sMeta[2];
    __shared__ int sTok[TILE_M];
    __shared__ float sWr[TILE_M];
    extern __shared__ float smem[];

    int tid = threadIdx.x;
    int row0 = blockIdx.x * TILE_M;
    int by = blockIdx.y;
    if (tid == 0) { int e, a; tile_meta(row0, e, a); sMeta[0] = e; sMeta[1] = a; }
    __syncthreads();
    int e = sMeta[0], active = sMeta[1];
    if (active <= 0) return;
    if (tid < TILE_M) {
        sTok[tid] = (tid < active) ? g_tok[row0 + tid] : 0;
        sWr[tid]  = (tid < active) ? g_wrow[row0 + tid] : 0.f;
    }
    __syncthreads();

    int lrow = tid >> 1, lpart = (tid & 1) * 16;
    const float* arow = g_act + (size_t)(row0 + lrow) * Hh + lpart;
    const float* brow = g_wlt + ((size_t)e * Dd + by*TILE_M + lrow) * Hh + lpart;
    uint32_t sA = smem_u32(smem) + (uint32_t)(lrow*LDT + lpart) * 4u;
    uint32_t sB = sA + TILE_F * 4u;

    int lane = tid & 31, warp = tid >> 5;
    int wr = warp >> 2, wc = warp & 3;
    float acc[4][4][4];
#pragma unroll
    for (int i = 0; i < 4; i++)
#pragma unroll
        for (int j = 0; j < 4; j++)
#pragma unroll
            for (int q = 0; q < 4; q++) acc[i][j][q] = 0.f;

    const int NCH = Hh / KCH;   // 16
#pragma unroll
    for (int i = 0; i < 4; i++) {
        CP_ASYNC16(sA + i*16, arow + i*4);
        CP_ASYNC16(sB + i*16, brow + i*4);
    }
    CP_COMMIT();
    for (int s = 0; s < NCH; s++) {
        int buf = s & 1;
        if (s + 1 < NCH) {
            uint32_t dA = smem_u32(smem) + (uint32_t)((1-buf)*2*TILE_F + lrow*LDT + lpart)*4u;
            uint32_t dB = dA + TILE_F * 4u;
            const float* ga = arow + (s+1)*KCH;
            const float* gb = brow + (s+1)*KCH;
#pragma unroll
            for (int i = 0; i < 4; i++) {
                CP_ASYNC16(dA + i*16, ga + i*4);
                CP_ASYNC16(dB + i*16, gb + i*4);
            }
            CP_COMMIT();
            CP_WAIT(1);
        } else {
            CP_WAIT(0);
        }
        __syncthreads();
        const float* As = smem + buf*2*TILE_F;
        compute_chunk(As, As + TILE_F, lane, wr, wc, acc);
        __syncthreads();
    }

    // epilogue: scale by wrow, atomic add into out (guard inactive rows)
    int rloc = wr*64 + (lane >> 2);
    int dbase = by*TILE_M + wc*32 + (lane & 3)*2;
#pragma unroll
    for (int mf = 0; mf < 4; mf++) {
#pragma unroll
        for (int half = 0; half < 2; half++) {
            int r = rloc + mf*16 + half*8;
            if (r < active) {
                float w = sWr[r];
                float* obase = out + (size_t)sTok[r] * Dd;
#pragma unroll
                for (int nf = 0; nf < 4; nf++) {
                    int d = dbase + nf*8;
                    atomicAdd(obase + d,     acc[mf][nf][half*2]     * w);
                    atomicAdd(obase + d + 1, acc[mf][nf][half*2 + 1] * w);
                }
            }
        }
    }
}

// ---------------- launch ----------------
extern "C" void kernel_launch(void* const* d_in, const int* in_sizes, int n_in,
                              void* d_out, int out_size) {
    const float* x   = (const float*)d_in[0];
    const float* wr  = (const float*)d_in[1];
    const float* wg  = (const float*)d_in[2];
    const float* wl  = (const float*)d_in[3];
    const float* pes = (const float*)d_in[4];
    const float* rsc = (const float*)d_in[5];
    float* out = (float*)d_out;

    const int smemB = 4 * TILE_F * sizeof(float);   // 73728
    cudaFuncSetAttribute(ffn1_mma, cudaFuncAttributeMaxDynamicSharedMemorySize, smemB);
    cudaFuncSetAttribute(ffn2_mma, cudaFuncAttributeMaxDynamicSharedMemorySize, smemB);

    cudaMemsetAsync(out, 0, (size_t)out_size * sizeof(float), 0);
    init_kernel<<<1, 32>>>();
    router_kernel<<<Bt / 8, 256>>>(x, wr, rsc);
    count_kernel<<<Bt / 256, 256>>>();
    prefix_kernel<<<1, 32>>>();
    scatter_kernel<<<Bt / 256, 256>>>(pes);
    transpose_wl_kernel<<<dim3(Hh/32, Dd/32, Ee), dim3(32, 8)>>>(wl);
    ffn1_mma<<<dim3(MAX_TILES, 8), 256, smemB>>>(x, wg);
    ffn2_mma<<<dim3(MAX_TILES, 2), 256, smemB>>>(out);
}